// round 7
// baseline (speedup 1.0000x reference)
#include <cuda_runtime.h>
#include <cuda_bf16.h>
#include <cstdint>

#define N_NODES 100000
#define N_EDGES 640000
#define D 128
#define SCAN_BS 1024
#define N_SCAN_BLOCKS ((N_NODES + SCAN_BS - 1) / SCAN_BS)  // 98
#define M_TILE 64
#define GEMM_BLOCKS ((N_NODES + M_TILE - 1) / M_TILE)      // 1563

// ---- scratch (device globals: no allocation allowed) ----
__device__ float g_h[(size_t)N_NODES * D];
__device__ float g_bufA[(size_t)N_NODES * D];
__device__ float g_bufB[(size_t)N_NODES * D];
__device__ int   g_deg[N_NODES];
__device__ float g_dinv[N_NODES];
__device__ int   g_rowptr[N_NODES + 1];
__device__ int   g_cursor[N_NODES];
__device__ int   g_bsum[128];
__device__ int   g_boff[128];
__device__ int   g_esrc[N_EDGES];
__device__ float g_enorm[N_EDGES];
__device__ int   g_ei[2 * N_EDGES];
// W transposed to [n][k], bf16 hi/lo split, pre-XOR-swizzled rows of 256B.
__device__ unsigned char g_wt[3 * 2 * 32768];

__device__ __forceinline__ uint32_t swz(int row, int kb) {
    return (uint32_t)(row * 256 + (kb ^ ((row & 7) << 4)));
}

__device__ __forceinline__ uint32_t s2u(const void* p) {
    uint32_t a;
    asm("{ .reg .u64 t; cvta.to.shared.u64 t, %1; cvt.u32.u64 %0, t; }"
        : "=r"(a) : "l"(p));
    return a;
}

#define LDSM_X4(d, a) \
    asm volatile("ldmatrix.sync.aligned.m8n8.x4.shared.b16 {%0,%1,%2,%3}, [%4];" \
        : "=r"((d)[0]), "=r"((d)[1]), "=r"((d)[2]), "=r"((d)[3]) : "r"(a))

#define MMA_BF16(c, a, b0, b1) \
    asm volatile("mma.sync.aligned.m16n8k16.row.col.f32.bf16.bf16.f32 " \
        "{%0,%1,%2,%3}, {%4,%5,%6,%7}, {%8,%9}, {%0,%1,%2,%3};" \
        : "+f"((c)[0]), "+f"((c)[1]), "+f"((c)[2]), "+f"((c)[3]) \
        : "r"((a)[0]), "r"((a)[1]), "r"((a)[2]), "r"((a)[3]), "r"(b0), "r"(b1))

#define CP_ASYNC16(dst, src) \
    asm volatile("cp.async.ca.shared.global [%0], [%1], 16;" :: "r"(dst), "l"(src))
#define CP_COMMIT() asm volatile("cp.async.commit_group;")
#define CP_WAIT0()  asm volatile("cp.async.wait_group 0;")

// ---------------- edge-index dtype sniff ----------------
__device__ __forceinline__ bool ei_is_int64(const int* __restrict__ w) {
    bool z = true;
#pragma unroll
    for (int i = 1; i < 32; i += 2) z &= (w[i] == 0);
    return z;
}

__global__ void k_convert_hist(const int* __restrict__ ei_raw, int* __restrict__ ei32,
                               int* __restrict__ deg) {
    int e = blockIdx.x * blockDim.x + threadIdx.x;
    if (e >= N_EDGES) return;
    bool is64 = ei_is_int64(ei_raw);
    int r = is64 ? ei_raw[2 * e] : ei_raw[e];
    int c = is64 ? ei_raw[2 * (N_EDGES + e)] : ei_raw[N_EDGES + e];
    ei32[e] = r;
    ei32[N_EDGES + e] = c;
    atomicAdd(&deg[c], 1);
}

// ---------------- W prep: transpose + bf16 hi/lo split + swizzle ----------------
__global__ void k_wprep(const float* __restrict__ W) {
    int i = blockIdx.x * blockDim.x + threadIdx.x;
    if (i >= 3 * 128 * 128) return;
    int l = i >> 14;
    int rem = i & 16383;
    int k = rem >> 7;
    int n = rem & 127;
    float w = W[l * 16384 + k * 128 + n];
    __nv_bfloat16 hb = __float2bfloat16_rn(w);
    float hf = __bfloat162float(hb);
    __nv_bfloat16 lb = __float2bfloat16_rn(w - hf);
    uint32_t pos = swz(n, k * 2);
    *(__nv_bfloat16*)(g_wt + (size_t)(l * 2 + 0) * 32768 + pos) = hb;
    *(__nv_bfloat16*)(g_wt + (size_t)(l * 2 + 1) * 32768 + pos) = lb;
}

// ---------------- prep ----------------
__global__ void k_zeroi(int* __restrict__ p, int n) {
    int i = blockIdx.x * blockDim.x + threadIdx.x;
    if (i < n) p[i] = 0;
}

__global__ __launch_bounds__(256) void k_dinv_bsum(const int* __restrict__ deg,
                                                   float* __restrict__ dinv,
                                                   int* __restrict__ bsum) {
    __shared__ int s[256];
    int b = blockIdx.x, t = threadIdx.x;
    int base = b * SCAN_BS + t * 4;
    int v = 0;
#pragma unroll
    for (int j = 0; j < 4; j++) {
        int i = base + j;
        if (i < N_NODES) {
            int d = deg[i];
            dinv[i] = (d > 0) ? rsqrtf((float)d) : 0.f;
            v += d;
        }
    }
    s[t] = v;
    __syncthreads();
    for (int off = 128; off > 0; off >>= 1) {
        if (t < off) s[t] += s[t + off];
        __syncthreads();
    }
    if (t == 0) bsum[b] = s[0];
}

__global__ __launch_bounds__(128) void k_scansums(const int* __restrict__ bsum,
                                                  int* __restrict__ boff,
                                                  int* __restrict__ rowptr) {
    __shared__ int s[128];
    int t = threadIdx.x;
    int v = (t < N_SCAN_BLOCKS) ? bsum[t] : 0;
    s[t] = v;
    __syncthreads();
    for (int off = 1; off < 128; off <<= 1) {
        int u = (t >= off) ? s[t - off] : 0;
        __syncthreads();
        s[t] += u;
        __syncthreads();
    }
    if (t < N_SCAN_BLOCKS) boff[t] = s[t] - v;
    if (t == N_SCAN_BLOCKS - 1) rowptr[N_NODES] = s[t];
}

__global__ __launch_bounds__(SCAN_BS) void k_scanapply(const int* __restrict__ deg,
                                                       const int* __restrict__ boff,
                                                       int* __restrict__ rowptr,
                                                       int* __restrict__ cursor) {
    __shared__ int s[SCAN_BS];
    int b = blockIdx.x, t = threadIdx.x;
    int i = b * SCAN_BS + t;
    int v = (i < N_NODES) ? deg[i] : 0;
    s[t] = v;
    __syncthreads();
    for (int off = 1; off < SCAN_BS; off <<= 1) {
        int u = (t >= off) ? s[t - off] : 0;
        __syncthreads();
        s[t] += u;
        __syncthreads();
    }
    if (i < N_NODES) {
        int excl = boff[b] + s[t] - v;
        rowptr[i] = excl;
        cursor[i] = excl;
    }
}

__global__ void k_fill(const int* __restrict__ ei, const float* __restrict__ dinv,
                       int* __restrict__ cursor, int* __restrict__ esrc,
                       float* __restrict__ enorm) {
    int e = blockIdx.x * blockDim.x + threadIdx.x;
    if (e >= N_EDGES) return;
    int r = ei[e];
    int c = ei[N_EDGES + e];
    int pos = atomicAdd(&cursor[c], 1);
    esrc[pos] = r;
    enorm[pos] = dinv[r] * dinv[c];
}

// ---------------- mma.sync GEMM: H = act(X) @ W, 3xBF16 split ----------------
// CTA: 64 rows x 128 cols, 128 threads = 4 warps (2m x 2n), warp tile m32 x n64.
// smem: A_hi 16KB | A_lo 16KB | W_hi 32KB | W_lo 32KB = 96KB (2 CTAs/SM).
#define OFF_AH 0u
#define OFF_AL 16384u
#define OFF_WH 32768u
#define OFF_WL 65536u
#define GEMM_SMEM 98304
#define GEMM_TPB 128

__device__ __forceinline__ uint2 pack4(float x, float y, float z, float w) {
    __nv_bfloat162 p0 = __floats2bfloat162_rn(x, y);
    __nv_bfloat162 p1 = __floats2bfloat162_rn(z, w);
    return make_uint2(*(uint32_t*)&p0, *(uint32_t*)&p1);
}

template <bool RELU>
__global__ __launch_bounds__(GEMM_TPB, 2) void k_gemm(const float* __restrict__ X,
                                                      int layer,
                                                      float* __restrict__ H) {
    extern __shared__ unsigned char smem[];
    const uint32_t sb = s2u(smem);
    const int tid = threadIdx.x;
    const int w = tid >> 5;
    const int lane = tid & 31;
    const int wm = w >> 1;      // 0..1
    const int wn = w & 1;       // 0..1
    const int row0 = blockIdx.x * M_TILE;

    // ---- kick off W copy via cp.async (overlaps with A staging below) ----
    {
        const unsigned char* sh = g_wt + (size_t)(layer * 2 + 0) * 32768;
        const unsigned char* sl = g_wt + (size_t)(layer * 2 + 1) * 32768;
#pragma unroll
        for (int j = 0; j < 16; j++) {
            uint32_t off = (uint32_t)(tid + j * 128) * 16;
            CP_ASYNC16(sb + OFF_WH + off, sh + off);
            CP_ASYNC16(sb + OFF_WL + off, sl + off);
        }
        CP_COMMIT();
    }

    // ---- stage A: 64 rows x 128, fused act + hi/lo split, swizzled ----
    {
        int r = tid >> 1;       // 0..63
        int q = tid & 1;
        int gr = row0 + r;
        bool valid = gr < N_NODES;
        const float4* src = (const float4*)(X + (size_t)gr * D);
#pragma unroll
        for (int j = 0; j < 16; j++) {
            int qp = q + j * 2;                    // float4 index 0..31
            float4 v = valid ? src[qp] : make_float4(0.f, 0.f, 0.f, 0.f);
            if (RELU) {
                v.x = fmaxf(v.x, 0.f); v.y = fmaxf(v.y, 0.f);
                v.z = fmaxf(v.z, 0.f); v.w = fmaxf(v.w, 0.f);
            }
            uint2 hi = pack4(v.x, v.y, v.z, v.w);
            float hx = __bfloat162float(__float2bfloat16_rn(v.x));
            float hy = __bfloat162float(__float2bfloat16_rn(v.y));
            float hz = __bfloat162float(__float2bfloat16_rn(v.z));
            float hw = __bfloat162float(__float2bfloat16_rn(v.w));
            uint2 lo = pack4(v.x - hx, v.y - hy, v.z - hz, v.w - hw);
            uint32_t addr = swz(r, qp * 8);
            *(uint2*)(smem + OFF_AH + addr) = hi;
            *(uint2*)(smem + OFF_AL + addr) = lo;
        }
    }
    CP_WAIT0();
    __syncthreads();

    float acc[2][8][4];
#pragma unroll
    for (int mi = 0; mi < 2; mi++)
#pragma unroll
        for (int ni = 0; ni < 8; ni++)
#pragma unroll
            for (int j = 0; j < 4; j++) acc[mi][ni][j] = 0.f;

    const int a_row = wm * 32 + (lane & 15);              // + mi*16
    const int a_kb  = (lane >> 4) << 4;                   // + ks*32
    const int b_row = wn * 64 + ((lane >> 4) << 3) + (lane & 7);  // + p*16
    const int b_kb  = ((lane >> 3) & 1) << 4;             // + ks*32

#pragma unroll
    for (int ks = 0; ks < 8; ks++) {
        uint32_t ah[2][4], al[2][4], bh[4][4], bl[4][4];
#pragma unroll
        for (int mi = 0; mi < 2; mi++) {
            uint32_t addr = swz(a_row + mi * 16, a_kb + ks * 32);
            LDSM_X4(ah[mi], sb + OFF_AH + addr);
            LDSM_X4(al[mi], sb + OFF_AL + addr);
        }
#pragma unroll
        for (int p = 0; p < 4; p++) {
            uint32_t addr = swz(b_row + p * 16, b_kb + ks * 32);
            LDSM_X4(bh[p], sb + OFF_WH + addr);
            LDSM_X4(bl[p], sb + OFF_WL + addr);
        }
#pragma unroll
        for (int mi = 0; mi < 2; mi++) {
#pragma unroll
            for (int p = 0; p < 4; p++) {
#pragma unroll
                for (int s = 0; s < 2; s++) {
                    int ni = p * 2 + s;
                    MMA_BF16(acc[mi][ni], ah[mi], bh[p][s * 2], bh[p][s * 2 + 1]);
                    MMA_BF16(acc[mi][ni], ah[mi], bl[p][s * 2], bl[p][s * 2 + 1]);
                    MMA_BF16(acc[mi][ni], al[mi], bh[p][s * 2], bh[p][s * 2 + 1]);
                }
            }
        }
    }

#pragma unroll
    for (int mi = 0; mi < 2; mi++) {
        int r1 = row0 + wm * 32 + mi * 16 + (lane >> 2);
        int r2 = r1 + 8;
#pragma unroll
        for (int ni = 0; ni < 8; ni++) {
            int col = wn * 64 + ni * 8 + 2 * (lane & 3);
            if (r1 < N_NODES)
                *(float2*)(H + (size_t)r1 * D + col) = make_float2(acc[mi][ni][0], acc[mi][ni][1]);
            if (r2 < N_NODES)
                *(float2*)(H + (size_t)r2 * D + col) = make_float2(acc[mi][ni][2], acc[mi][ni][3]);
        }
    }
}

// ---------------- CSR gather ----------------
__global__ __launch_bounds__(256) void k_gather(const int* __restrict__ rowptr,
                                                const int* __restrict__ esrc,
                                                const float* __restrict__ enorm,
                                                const float* __restrict__ H,
                                                const float* __restrict__ bvec,
                                                float* __restrict__ out) {
    int n = blockIdx.x * 8 + (threadIdx.x >> 5);
    if (n >= N_NODES) return;
    int lane = threadIdx.x & 31;

    float4 acc = ((const float4*)bvec)[lane];

    int e = rowptr[n];
    int end = rowptr[n + 1];
    for (; e + 4 <= end; e += 4) {
        int s0 = esrc[e], s1 = esrc[e + 1], s2 = esrc[e + 2], s3 = esrc[e + 3];
        float n0 = enorm[e], n1 = enorm[e + 1], n2 = enorm[e + 2], n3 = enorm[e + 3];
        float4 v0 = __ldg(&((const float4*)(H + (size_t)s0 * D))[lane]);
        float4 v1 = __ldg(&((const float4*)(H + (size_t)s1 * D))[lane]);
        float4 v2 = __ldg(&((const float4*)(H + (size_t)s2 * D))[lane]);
        float4 v3 = __ldg(&((const float4*)(H + (size_t)s3 * D))[lane]);
        acc.x += v0.x * n0 + v1.x * n1 + v2.x * n2 + v3.x * n3;
        acc.y += v0.y * n0 + v1.y * n1 + v2.y * n2 + v3.y * n3;
        acc.z += v0.z * n0 + v1.z * n1 + v2.z * n2 + v3.z * n3;
        acc.w += v0.w * n0 + v1.w * n1 + v2.w * n2 + v3.w * n3;
    }
    for (; e < end; e++) {
        int s0 = esrc[e];
        float n0 = enorm[e];
        float4 v0 = __ldg(&((const float4*)(H + (size_t)s0 * D))[lane]);
        acc.x += v0.x * n0; acc.y += v0.y * n0;
        acc.z += v0.z * n0; acc.w += v0.w * n0;
    }
    ((float4*)(out + (size_t)n * D))[lane] = acc;
}

// ---------------- launch ----------------
extern "C" void kernel_launch(void* const* d_in, const int* in_sizes, int n_in,
                              void* d_out, int out_size) {
    const float* x = (const float*)d_in[0];
    const int* ei_raw = (const int*)d_in[1];
    const float* W = (const float*)d_in[3];
    const float* b = (const float*)d_in[4];
    float* out = (float*)d_out;

    float *dinv, *h, *bufA, *bufB, *enorm;
    int *deg, *rowptr, *cursor, *bsum, *boff, *esrc, *ei;
    cudaGetSymbolAddress((void**)&dinv, g_dinv);
    cudaGetSymbolAddress((void**)&h, g_h);
    cudaGetSymbolAddress((void**)&bufA, g_bufA);
    cudaGetSymbolAddress((void**)&bufB, g_bufB);
    cudaGetSymbolAddress((void**)&enorm, g_enorm);
    cudaGetSymbolAddress((void**)&deg, g_deg);
    cudaGetSymbolAddress((void**)&rowptr, g_rowptr);
    cudaGetSymbolAddress((void**)&cursor, g_cursor);
    cudaGetSymbolAddress((void**)&bsum, g_bsum);
    cudaGetSymbolAddress((void**)&boff, g_boff);
    cudaGetSymbolAddress((void**)&esrc, g_esrc);
    cudaGetSymbolAddress((void**)&ei, g_ei);

    cudaFuncSetAttribute(k_gemm<false>, cudaFuncAttributeMaxDynamicSharedMemorySize, GEMM_SMEM);
    cudaFuncSetAttribute(k_gemm<true>, cudaFuncAttributeMaxDynamicSharedMemorySize, GEMM_SMEM);

    const int TPB = 256;
    const int GATH_BLOCKS = (N_NODES + 7) / 8;

    // fork a side stream: wprep + layer-0 GEMM overlap the edge-prep chain
    cudaStream_t s2;
    cudaEvent_t evFork, evJoin;
    cudaStreamCreateWithFlags(&s2, cudaStreamNonBlocking);
    cudaEventCreateWithFlags(&evFork, cudaEventDisableTiming);
    cudaEventCreateWithFlags(&evJoin, cudaEventDisableTiming);

    cudaEventRecord(evFork, 0);
    cudaStreamWaitEvent(s2, evFork, 0);

    k_wprep<<<(3 * 128 * 128 + TPB - 1) / TPB, TPB, 0, s2>>>(W);
    k_gemm<false><<<GEMM_BLOCKS, GEMM_TPB, GEMM_SMEM, s2>>>(x, 0, h);
    cudaEventRecord(evJoin, s2);

    k_zeroi<<<(N_NODES + TPB - 1) / TPB, TPB>>>(deg, N_NODES);
    k_convert_hist<<<(N_EDGES + TPB - 1) / TPB, TPB>>>(ei_raw, ei, deg);
    k_dinv_bsum<<<N_SCAN_BLOCKS, 256>>>(deg, dinv, bsum);
    k_scansums<<<1, 128>>>(bsum, boff, rowptr);
    k_scanapply<<<N_SCAN_BLOCKS, SCAN_BS>>>(deg, boff, rowptr, cursor);
    k_fill<<<(N_EDGES + TPB - 1) / TPB, TPB>>>(ei, dinv, cursor, esrc, enorm);

    cudaStreamWaitEvent(0, evJoin, 0);

    k_gather<<<GATH_BLOCKS, TPB>>>(rowptr, esrc, enorm, h, b + 0 * D, bufA);
    k_gemm<true><<<GEMM_BLOCKS, GEMM_TPB, GEMM_SMEM>>>(bufA, 1, h);
    k_gather<<<GATH_BLOCKS, TPB>>>(rowptr, esrc, enorm, h, b + 1 * D, bufB);
    k_gemm<true><<<GEMM_BLOCKS, GEMM_TPB, GEMM_SMEM>>>(bufB, 2, h);
    k_gather<<<GATH_BLOCKS, TPB>>>(rowptr, esrc, enorm, h, b + 2 * D, out);
}